// round 6
// baseline (speedup 1.0000x reference)
#include <cuda_runtime.h>
#include <math.h>

// ---------------------------------------------------------------------------
// MetaLearner: coordinate-wise LSTM learned optimizer, 16 sequential steps.
// D=512, C=256, U=40, T=16, B=64, P=131072, 4 groups sharing weights.
// ---------------------------------------------------------------------------

#define D 512
#define C 256
#define U 40
#define T 16
#define B 64
#define P 131072
#define NZ 160              // 4*U
#define KE 43               // 3 + U   (l0,l1 folded into bias)
#define PREP 10.0f

#define NEGEXPP 4.5399929762484854e-05f   // exp(-10)
#define EXPP    22026.465794806718f       // exp(+10)

#define NBLK_C 444          // 3 blocks per SM

// ---------------- persistent state (no allocations allowed) ----------------
__device__ float g_h[(size_t)U * P];     // transposed [U][P]
__device__ float g_c[(size_t)U * P];
__device__ float g_p[P];
__device__ float g_f[P];
__device__ float g_i[P];
__device__ __align__(16) float g_e[B * C];
__device__ float g_losspart[128];

// ---------------------------------------------------------------------------
// FMA/ALU-only tanh (no MUFU).
// ---------------------------------------------------------------------------
__device__ __forceinline__ float tanh_fma(float x)
{
    float xc = fminf(fmaxf(x, -9.0f), 9.0f);
    float y  = xc * 2.8853900817779268f;          // 2*log2(e)*x
    float r  = __fadd_rn(y, 12582912.0f);         // 1.5*2^23
    int   n  = __float_as_int(r) - 0x4B400000;
    float f  = y - __fadd_rn(r, -12582912.0f);    // f in [-0.5, 0.5]
    float p  = 1.5403530393e-4f;
    p = fmaf(p, f, 1.3333558146e-3f);
    p = fmaf(p, f, 9.6181291076e-3f);
    p = fmaf(p, f, 5.5504108665e-2f);
    p = fmaf(p, f, 2.4022650696e-1f);
    p = fmaf(p, f, 6.9314718056e-1f);
    p = fmaf(p, f, 1.0f);
    float e  = __int_as_float(__float_as_int(p) + (n << 23));  // exp(2x)
    float d  = e + 1.0f;
    float rc = __int_as_float(0x7EF311C3 - __float_as_int(d));
    rc = rc * fmaf(-d, rc, 2.0f);
    rc = rc * fmaf(-d, rc, 2.0f);
    rc = rc * fmaf(-d, rc, 2.0f);
    return fmaf(-2.0f, rc, 1.0f);                 // 1 - 2/(e+1)
}

__device__ __forceinline__ float hsig(float x)
{
    return __saturatef(fmaf(0.2f, x, 0.5f));
}

#define FMA2(acc, a, b) \
    asm("fma.rn.f32x2 %0, %1, %2, %0;" : "+l"(acc) : "l"(a), "l"(b))

__device__ __forceinline__ float2 u2f(unsigned long long v)
{
    float2 r;
    asm("mov.b64 {%0, %1}, %2;" : "=f"(r.x), "=f"(r.y) : "l"(v));
    return r;
}
__device__ __forceinline__ unsigned long long pack2(float a, float b)
{
    unsigned long long v;
    asm("mov.b64 %0, {%1, %2};" : "=l"(v) : "f"(a), "f"(b));
    return v;
}

// ---------------------------------------------------------------------------
// Kernel A: preds/e/loss-partials.  grid 128 = b(64) x col-half(2), 256 thr.
// ---------------------------------------------------------------------------
__global__ void __launch_bounds__(256) stepA(
    const float* __restrict__ feats_t,
    const float* __restrict__ labels_t,
    const float* __restrict__ params, int t0)
{
    __shared__ float fr[D];
    __shared__ float4 sred[256];
    int tid = threadIdx.x;
    int b = blockIdx.x >> 1;
    int half = blockIdx.x & 1;

    fr[tid] = feats_t[b * D + tid];
    fr[tid + 256] = feats_t[b * D + tid + 256];
    __syncthreads();

    const float* pm = t0 ? params : g_p;
    const float4* pm4 = (const float4*)pm;
    int q = tid & 31;
    int c4 = half * 32 + q;
    int ks = tid >> 5;
    float4 acc = make_float4(0.f, 0.f, 0.f, 0.f);
    int dbeg = ks * 64;
#pragma unroll 8
    for (int d = dbeg; d < dbeg + 64; d++) {
        float fv = fr[d];
        float4 w = pm4[d * 64 + c4];
        acc.x = fmaf(fv, w.x, acc.x);
        acc.y = fmaf(fv, w.y, acc.y);
        acc.z = fmaf(fv, w.z, acc.z);
        acc.w = fmaf(fv, w.w, acc.w);
    }
    sred[tid] = acc;
    __syncthreads();

    if (tid < 32) {
        float4 s = sred[tid];
#pragma unroll
        for (int k = 1; k < 8; k++) {
            float4 a = sred[tid + 32 * k];
            s.x += a.x; s.y += a.y; s.z += a.z; s.w += a.w;
        }
        int cc = half * 32 + tid;
        float4 y = ((const float4*)labels_t)[b * 64 + cc];
        float4 df = make_float4(s.x - y.x, s.y - y.y, s.z - y.z, s.w - y.w);
        const float kc = 2.0f / 16384.0f;
        ((float4*)g_e)[b * 64 + cc] =
            make_float4(df.x * kc, df.y * kc, df.z * kc, df.w * kc);
        float v = df.x * df.x + df.y * df.y + df.z * df.z + df.w * df.w;
#pragma unroll
        for (int off = 16; off > 0; off >>= 1)
            v += __shfl_xor_sync(0xffffffffu, v, off);
        if (tid == 0) g_losspart[blockIdx.x] = v;
    }
}

// ---------------------------------------------------------------------------
// Kernel C: grads + LSTM + param update. grid = 444 blocks (3/SM) x 256 thr.
// Gate-paired FFMA2, pre-splatted x in smem (1 LDS.128/k for x),
// register-preloaded epilogue operands, c prefetch, 2 barriers/tile with
// epilogue overlapped with next tile's fill.
// ---------------------------------------------------------------------------
#define WP_ULL    (KE * 80)                  // 3440 ull weight pairs
#define BP_OFF    WP_ULL                     // 80 ull bias pairs
#define XS2_OFF   (WP_ULL + 80)              // 2752 ull splatted x
#define ULL_TOT   (XS2_OFF + KE * 64)        // 6272
#define F_WF      0
#define F_WI      41
#define F_SCAL    82
#define F_FCOL    88                          // [3][64] = 192
#define F_GBUF    (F_FCOL + 192)              // 320 floats (nc<=320)
#define F_PR      (F_GBUF + 320)              // 1024 floats
#define F_TOT     (F_PR + 1024)
#define SMEM_C_BYTES (ULL_TOT * 8 + F_TOT * 4)   // 50176+6496=56672

__global__ void __launch_bounds__(256, 3) stepC(
    const float* __restrict__ feats_t, // [64,512]
    const float* __restrict__ kern,    // [4,5,160]
    const float* __restrict__ rkern,   // [4,40,160]
    const float* __restrict__ bias,    // [4,160]
    const float* __restrict__ Wf,      // [4,41]
    const float* __restrict__ bf,      // [4]
    const float* __restrict__ Wi,      // [4,41]
    const float* __restrict__ bi,      // [4]
    const float* __restrict__ params,  // [P]
    float* __restrict__ outp,
    int t0, int last)
{
    extern __shared__ __align__(16) unsigned long long smU[];
    unsigned long long* Wp  = smU;            // [43][8][10]
    unsigned long long* bp  = smU + BP_OFF;   // [8][10]
    unsigned long long* xs2 = smU + XS2_OFF;  // [43][64] splatted
    float* smF  = (float*)(smU + ULL_TOT);
    float* Wf_s = smF + F_WF;
    float* Wi_s = smF + F_WI;
    float* scal = smF + F_SCAL;
    float* fcol = smF + F_FCOL;
    float* gbuf = smF + F_GBUF;
    float2* prF = (float2*)(smF + F_PR);          // [8][32]
    float2* prI = (float2*)(smF + F_PR + 512);    // [8][32]

    int tid = threadIdx.x;
    int blk = blockIdx.x;

    // ---- block -> (group, tile range) ----
    int grp, bi_, nb, nt, t0g;
    if (blk < 56)       { grp = 0; bi_ = blk;       nb = 56;  nt = 256; t0g = 0;    }
    else if (blk < 167) { grp = 1; bi_ = blk - 56;  nb = 111; nt = 512; t0g = 256;  }
    else if (blk < 333) { grp = 2; bi_ = blk - 167; nb = 166; nt = 768; t0g = 768;  }
    else                { grp = 3; bi_ = blk - 333; nb = 111; nt = 512; t0g = 1536; }
    int q = nt / nb, r = nt % nb;
    int tile_start = t0g + bi_ * q + min(bi_, r);
    int ntiles = q + (bi_ < r ? 1 : 0);          // 4 or 5
    int start64 = tile_start * 64;
    int nc = ntiles * 64;                        // <= 320

    // ---- phase 0a: weights (gate-paired), Wf/Wi, fcol, constants ----
    if (tid < 41) { Wf_s[tid] = Wf[grp * 41 + tid]; Wi_s[tid] = Wi[grp * 41 + tid]; }
    if (tid == 0) { scal[2] = bf[grp]; scal[3] = bi[grp]; }
    int d_lo = start64 >> 8;
    int d_hi = (start64 + nc - 1) >> 8;
    int nd = d_hi - d_lo + 1;                     // <= 3
    for (int idx = tid; idx < nd * 64; idx += 256) {
        int bb = idx & 63, k = idx >> 6;
        fcol[k * 64 + bb] = feats_t[bb * D + d_lo + k];
    }
    // Wp[k][tn][j]: j=2*uu+p; p=0 -> (w_i,w_f); p=1 -> (w_c,w_o)
    for (int idx = tid; idx < KE * 80; idx += 256) {
        int k = idx / 80, j8 = idx - k * 80;
        int tn_ = j8 / 10, j = j8 - tn_ * 10;
        int uu = j >> 1, p = j & 1;
        int u = tn_ * 5 + uu;
        int n0 = (p ? 2 : 0) * 40 + u;
        int n1 = (p ? 3 : 1) * 40 + u;
        const float* src = (k < 3) ? (kern + grp * 800 + k * NZ)
                                   : (rkern + grp * 6400 + (k - 3) * NZ);
        Wp[idx] = pack2(src[n0], src[n1]);
    }
    __syncthreads();

    // ---- phase 0b: loss reduce (warp 0) + grads into gbuf (all) ----
    if (tid < 32) {
        float v = g_losspart[tid] + g_losspart[tid + 32]
                + g_losspart[tid + 64] + g_losspart[tid + 96];
#pragma unroll
        for (int off = 16; off > 0; off >>= 1)
            v += __shfl_xor_sync(0xffffffffu, v, off);
        if (tid == 0) {
            float L = v * (1.0f / 16384.0f);
            float a = fabsf(L);
            if (a > NEGEXPP) {
                scal[0] = logf(a) / PREP;
                scal[1] = (L > 0.f) ? 1.f : ((L < 0.f) ? -1.f : 0.f);
            } else {
                scal[0] = -1.f;
                scal[1] = EXPP * L;
            }
        }
    }
    {
        int cc = (start64 + tid) & 255;
        float acc0 = 0.f, acc1 = 0.f;
        int dk0 = ((start64 + tid) >> 8) - d_lo;
        int dk1 = dk0 + 1;
        int n1 = nc - 256;
#pragma unroll 8
        for (int bb = 0; bb < B; bb++) {
            float ev = g_e[bb * C + cc];
            acc0 = fmaf(fcol[dk0 * 64 + bb], ev, acc0);
            if (tid < n1) acc1 = fmaf(fcol[dk1 * 64 + bb], ev, acc1);
        }
        gbuf[tid] = acc0;
        if (tid < n1) gbuf[tid + 256] = acc1;
    }
    __syncthreads();

    // ---- phase 0c: effective bias (l0,l1 folded), gate-paired ----
    float l0 = scal[0], l1 = scal[1], bfv = scal[2], biv = scal[3];
    if (tid < 80) {
        int tn_ = tid / 10, j = tid - tn_ * 10;
        int uu = j >> 1, p = j & 1;
        int u = tn_ * 5 + uu;
        int n0 = (p ? 2 : 0) * 40 + u;
        int n1 = (p ? 3 : 1) * 40 + u;
        const float* kb = kern + grp * 800;
        float b0 = bias[grp * NZ + n0] + l0 * kb[3 * NZ + n0] + l1 * kb[4 * NZ + n0];
        float b1 = bias[grp * NZ + n1] + l0 * kb[3 * NZ + n1] + l1 * kb[4 * NZ + n1];
        bp[tid] = pack2(b0, b1);
    }

    int tm = tid & 31;            // coord pair (2tm, 2tm+1)
    int tn = tid >> 5;            // u-range tn*5..tn*5+4
    int u0 = tn * 5;
    const unsigned long long* wthr = Wp + tn * 10;
    const unsigned long long* bthr = bp + tn * 10;

    float pold_r = 0.f, gv_r = 0.f, fp_r = 0.f, ip_r = 0.f;

    // ---- fill tile 0 + preload epilogue regs ----
    {
        int base = start64;
        if (tid < 64) {
            int coord = base + tid;
            pold_r = t0 ? params[coord] : g_p[coord];
            gv_r = gbuf[tid];
            fp_r = t0 ? 0.f : g_f[coord];
            ip_r = t0 ? 0.f : g_i[coord];
            float a = fabsf(gv_r);
            float g0, g1;
            if (a > NEGEXPP) {
                g0 = logf(a) / PREP;
                g1 = (gv_r > 0.f) ? 1.f : ((gv_r < 0.f) ? -1.f : 0.f);
            } else {
                g0 = -1.f;
                g1 = EXPP * gv_r;
            }
            xs2[tid]       = pack2(pold_r, pold_r);
            xs2[64 + tid]  = pack2(g0, g0);
            xs2[128 + tid] = pack2(g1, g1);
        }
        for (int idx = tid; idx < 32 * U; idx += 256) {
            int u = idx >> 5, m2 = idx & 31;
            float2 hv = t0 ? make_float2(0.f, 0.f)
                           : *(const float2*)(g_h + (size_t)u * P + base + 2 * m2);
            ulonglong2 v;
            v.x = pack2(hv.x, hv.x);
            v.y = pack2(hv.y, hv.y);
            *(ulonglong2*)(xs2 + (3 + u) * 64 + 2 * m2) = v;
        }
    }

    for (int it = 0; it < ntiles; it++) {
        int base = start64 + it * 64;
        __syncthreads();                       // barA: fill + prev epilogue done

        // ---- c prefetch (hidden under GEMM) ----
        float2 cpre[5];
#pragma unroll
        for (int uu = 0; uu < 5; uu++) {
            size_t off = (size_t)(u0 + uu) * P + base + 2 * tm;
            cpre[uu] = t0 ? make_float2(0.f, 0.f)
                          : *(const float2*)(g_c + off);
        }

        // ---- GEMM: gate-paired FFMA2, splatted x via LDS.128 ----
        unsigned long long acc[20];
#pragma unroll
        for (int j = 0; j < 10; j++) {
            unsigned long long bv = bthr[j];
            acc[j] = bv; acc[10 + j] = bv;
        }

        const ulonglong2* xrow = (const ulonglong2*)xs2 + tm;
#pragma unroll 2
        for (int k = 0; k < KE; k++) {
            ulonglong2 xv = xrow[k * 32];
            unsigned long long s0 = xv.x, s1 = xv.y;
            const unsigned long long* wp = wthr + k * 80;
            ulonglong2 w01 = *(const ulonglong2*)(wp);
            ulonglong2 w23 = *(const ulonglong2*)(wp + 2);
            ulonglong2 w45 = *(const ulonglong2*)(wp + 4);
            ulonglong2 w67 = *(const ulonglong2*)(wp + 6);
            ulonglong2 w89 = *(const ulonglong2*)(wp + 8);
            FMA2(acc[0], s0, w01.x);  FMA2(acc[10], s1, w01.x);
            FMA2(acc[1], s0, w01.y);  FMA2(acc[11], s1, w01.y);
            FMA2(acc[2], s0, w23.x);  FMA2(acc[12], s1, w23.x);
            FMA2(acc[3], s0, w23.y);  FMA2(acc[13], s1, w23.y);
            FMA2(acc[4], s0, w45.x);  FMA2(acc[14], s1, w45.x);
            FMA2(acc[5], s0, w45.y);  FMA2(acc[15], s1, w45.y);
            FMA2(acc[6], s0, w67.x);  FMA2(acc[16], s1, w67.x);
            FMA2(acc[7], s0, w67.y);  FMA2(acc[17], s1, w67.y);
            FMA2(acc[8], s0, w89.x);  FMA2(acc[18], s1, w89.x);
            FMA2(acc[9], s0, w89.y);  FMA2(acc[19], s1, w89.y);
        }

        // ---- gates + cell update + f/i partials (registers) ----
        float pf0 = 0.f, pf1 = 0.f, pi0 = 0.f, pi1 = 0.f;
#pragma unroll
        for (int uu = 0; uu < 5; uu++) {
            int u = u0 + uu;
            float2 if0 = u2f(acc[2 * uu]);        // m0: (z_i, z_f)
            float2 co0 = u2f(acc[2 * uu + 1]);    // m0: (z_c, z_o)
            float2 if1 = u2f(acc[10 + 2 * uu]);   // m1
            float2 co1 = u2f(acc[10 + 2 * uu + 1]);
            size_t off = (size_t)u * P + base + 2 * tm;
            float2 cp = cpre[uu];
            float cn0 = fmaf(hsig(if0.y), cp.x, hsig(if0.x) * tanh_fma(co0.x));
            float cn1 = fmaf(hsig(if1.y), cp.y, hsig(if1.x) * tanh_fma(co1.x));
            float hn0 = hsig(co0.y) * tanh_fma(cn0);
            float hn1 = hsig(co1.y) * tanh_fma(cn1);
            *(float2*)(g_c + off) = make_float2(cn0, cn1);
            *(float2*)(g_h + off) = make_float2(hn0, hn1);
            float wf = Wf_s[u], wi = Wi_s[u];
            pf0 = fmaf(hn0, wf, pf0);
            pf1 = fmaf(hn1, wf, pf1);
            pi0 = fmaf(hn0, wi, pi0);
            pi1 = fmaf(hn1, wi, pi1);
        }
        prF[tn * 32 + tm] = make_float2(pf0, pf1);
        prI[tn * 32 + tm] = make_float2(pi0, pi1);
        __syncthreads();                       // barB: pr written, xs2 free

        // ---- epilogue (tid < 64), overlapped with next fill ----
        if (tid < 64) {
            int m = tid;
            int coord = base + m;
            int half_ = m & 1, mp = m >> 1;
            float pf = 0.f, pi = 0.f;
#pragma unroll
            for (int w = 0; w < 8; w++) {
                float2 vf = prF[w * 32 + mp];
                float2 vi = prI[w * 32 + mp];
                pf += half_ ? vf.y : vf.x;
                pi += half_ ? vi.y : vi.x;
            }
            float fnew = fmaxf(fmaf(fp_r, Wf_s[40], pf) + bfv, 0.f);
            float inew = fmaxf(fmaf(ip_r, Wi_s[40], pi) + biv, 0.f);
            float pnew = fnew * pold_r - inew * gv_r;
            g_f[coord] = fnew;
            g_i[coord] = inew;
            if (last) outp[coord] = pnew;
            else      g_p[coord] = pnew;
        }

        // ---- fill next tile + preload next epilogue regs ----
        if (it + 1 < ntiles) {
            int nbase = base + 64;
            int nrel = (it + 1) * 64;
            if (tid < 64) {
                int coord = nbase + tid;
                pold_r = t0 ? params[coord] : g_p[coord];
                gv_r = gbuf[nrel + tid];
                fp_r = t0 ? 0.f : g_f[coord];
                ip_r = t0 ? 0.f : g_i[coord];
                float a = fabsf(gv_r);
                float g0, g1;
                if (a > NEGEXPP) {
                    g0 = logf(a) / PREP;
                    g1 = (gv_r > 0.f) ? 1.f : ((gv_r < 0.f) ? -1.f : 0.f);
                } else {
                    g0 = -1.f;
                    g1 = EXPP * gv_r;
                }
                xs2[tid]       = pack2(pold_r, pold_r);
                xs2[64 + tid]  = pack2(g0, g0);
                xs2[128 + tid] = pack2(g1, g1);
            }
            for (int idx = tid; idx < 32 * U; idx += 256) {
                int u = idx >> 5, m2 = idx & 31;
                float2 hv = t0 ? make_float2(0.f, 0.f)
                               : *(const float2*)(g_h + (size_t)u * P + nbase + 2 * m2);
                ulonglong2 v;
                v.x = pack2(hv.x, hv.x);
                v.y = pack2(hv.y, hv.y);
                *(ulonglong2*)(xs2 + (3 + u) * 64 + 2 * m2) = v;
            }
        }
    }
}

// ---------------------------------------------------------------------------
extern "C" void kernel_launch(void* const* d_in, const int* in_sizes, int n_in,
                              void* d_out, int out_size)
{
    const float* feats  = (const float*)d_in[0];
    const float* labels = (const float*)d_in[1];
    const float* params = (const float*)d_in[2];
    const float* kern   = (const float*)d_in[3];
    const float* rkern  = (const float*)d_in[4];
    const float* bias   = (const float*)d_in[5];
    const float* Wf     = (const float*)d_in[6];
    const float* bf     = (const float*)d_in[7];
    const float* Wi     = (const float*)d_in[8];
    const float* bi     = (const float*)d_in[9];
    float* out = (float*)d_out;

    cudaFuncSetAttribute(stepC, cudaFuncAttributeMaxDynamicSharedMemorySize,
                         SMEM_C_BYTES);

    for (int t = 0; t < T; t++) {
        const float* ft = feats  + (size_t)t * B * D;
        const float* lt = labels + (size_t)t * B * C;
        int t0 = (t == 0) ? 1 : 0;
        int last = (t == T - 1) ? 1 : 0;
        stepA<<<128, 256>>>(ft, lt, params, t0);
        stepC<<<NBLK_C, 256, SMEM_C_BYTES>>>(ft, kern, rkern, bias,
                                             Wf, bf, Wi, bi,
                                             params, out, t0, last);
    }
}